// round 3
// baseline (speedup 1.0000x reference)
#include <cuda_runtime.h>
#include <cstdint>

#define BATCH 64
#define S_LEN 2048
#define HID   256

// ---------------------------------------------------------------------------
// f32x2 packed-math helpers
// ---------------------------------------------------------------------------
__device__ __forceinline__ unsigned long long fma2(unsigned long long a,
                                                   unsigned long long b,
                                                   unsigned long long c) {
    unsigned long long d;
    asm("fma.rn.f32x2 %0, %1, %2, %3;" : "=l"(d) : "l"(a), "l"(b), "l"(c));
    return d;
}
__device__ __forceinline__ unsigned long long add2(unsigned long long a,
                                                   unsigned long long b) {
    unsigned long long d;
    asm("add.rn.f32x2 %0, %1, %2;" : "=l"(d) : "l"(a), "l"(b));
    return d;
}
__device__ __forceinline__ unsigned long long pack2(float x, float y) {
    unsigned long long r;
    asm("mov.b64 %0, {%1, %2};" : "=l"(r) : "f"(x), "f"(y));
    return r;
}
__device__ __forceinline__ float2 unpack2(unsigned long long v) {
    float2 r;
    asm("mov.b64 {%0, %1}, %2;" : "=f"(r.x), "=f"(r.y) : "l"(v));
    return r;
}

__device__ __forceinline__ unsigned smem_u32(const void* p) {
    return (unsigned)__cvta_generic_to_shared(p);
}
__device__ __forceinline__ unsigned mapa_peer(unsigned addr, unsigned rank) {
    unsigned r;
    asm("mapa.shared::cluster.u32 %0, %1, %2;" : "=r"(r) : "r"(addr), "r"(rank));
    return r;
}
__device__ __forceinline__ void st_cluster_f32(unsigned addr, float v) {
    asm volatile("st.shared::cluster.f32 [%0], %1;" :: "r"(addr), "f"(v) : "memory");
}
__device__ __forceinline__ void st_release_cluster_u32(unsigned addr, unsigned v) {
    asm volatile("st.release.cluster.shared::cluster.b32 [%0], %1;"
                 :: "r"(addr), "r"(v) : "memory");
}
__device__ __forceinline__ unsigned ld_acquire_cluster_u32(unsigned addr) {
    unsigned v;
    asm volatile("ld.acquire.cluster.shared::cta.b32 %0, [%1];"
                 : "=r"(v) : "r"(addr) : "memory");
    return v;
}
__device__ __forceinline__ void cluster_sync_all() {
    asm volatile("barrier.cluster.arrive.aligned;" ::: "memory");
    asm volatile("barrier.cluster.wait.aligned;" ::: "memory");
}
__device__ __forceinline__ void bar_sync(int id, int cnt) {
    asm volatile("bar.sync %0, %1;" :: "r"(id), "r"(cnt) : "memory");
}
__device__ __forceinline__ void bar_arrive(int id, int cnt) {
    asm volatile("bar.arrive %0, %1;" :: "r"(id), "r"(cnt) : "memory");
}

// ---------------------------------------------------------------------------
// Kernel 1: xW = X @ W_ih^T   (131072x256 @ 256x256) fp32, written into d_out
// ---------------------------------------------------------------------------
__global__ void __launch_bounds__(256) xw_gemm(const float* __restrict__ X,
                                               const float* __restrict__ Wih,
                                               float* __restrict__ out) {
    __shared__ alignas(16) float Xs[32][68];
    __shared__ alignas(16) float Ws[32][68];

    const int tid = threadIdx.x;
    const int m0  = blockIdx.x * 64;
    const int h0  = blockIdx.y * 64;
    const int row = tid >> 2;
    const int c4  = tid & 3;
    const int tx  = tid & 15;
    const int ty  = tid >> 4;

    unsigned long long acc[4][2];
#pragma unroll
    for (int i = 0; i < 4; i++) { acc[i][0] = 0ull; acc[i][1] = 0ull; }

    const float* Xbase = X   + (size_t)(m0 + row) * 256;
    const float* Wbase = Wih + (size_t)(h0 + row) * 256;

    float4 xa = *(const float4*)(Xbase + 0  + c4 * 4);
    float4 xb = *(const float4*)(Xbase + 16 + c4 * 4);
    float4 wa = *(const float4*)(Wbase + 0  + c4 * 4);
    float4 wb = *(const float4*)(Wbase + 16 + c4 * 4);

#pragma unroll 1
    for (int k0 = 0; k0 < 256; k0 += 32) {
        __syncthreads();
#pragma unroll
        for (int e = 0; e < 4; e++) {
            Xs[c4 * 4 + e][row]      = (&xa.x)[e];
            Xs[16 + c4 * 4 + e][row] = (&xb.x)[e];
            Ws[c4 * 4 + e][row]      = (&wa.x)[e];
            Ws[16 + c4 * 4 + e][row] = (&wb.x)[e];
        }
        float4 nxa = make_float4(0, 0, 0, 0), nxb = nxa, nwa = nxa, nwb = nxa;
        if (k0 < 224) {
            nxa = *(const float4*)(Xbase + k0 + 32 + c4 * 4);
            nxb = *(const float4*)(Xbase + k0 + 48 + c4 * 4);
            nwa = *(const float4*)(Wbase + k0 + 32 + c4 * 4);
            nwb = *(const float4*)(Wbase + k0 + 48 + c4 * 4);
        }
        __syncthreads();

#pragma unroll
        for (int kk = 0; kk < 32; kk++) {
            float4 a4 = *(const float4*)(&Xs[kk][ty * 4]);
            const unsigned long long* bp =
                (const unsigned long long*)(&Ws[kk][tx * 4]);
            unsigned long long b0 = bp[0];
            unsigned long long b1 = bp[1];
            unsigned long long aa;
            aa = pack2(a4.x, a4.x);
            acc[0][0] = fma2(aa, b0, acc[0][0]); acc[0][1] = fma2(aa, b1, acc[0][1]);
            aa = pack2(a4.y, a4.y);
            acc[1][0] = fma2(aa, b0, acc[1][0]); acc[1][1] = fma2(aa, b1, acc[1][1]);
            aa = pack2(a4.z, a4.z);
            acc[2][0] = fma2(aa, b0, acc[2][0]); acc[2][1] = fma2(aa, b1, acc[2][1]);
            aa = pack2(a4.w, a4.w);
            acc[3][0] = fma2(aa, b0, acc[3][0]); acc[3][1] = fma2(aa, b1, acc[3][1]);
        }
        xa = nxa; xb = nxb; wa = nwa; wb = nwb;
    }

#pragma unroll
    for (int i = 0; i < 4; i++) {
        float2 p = unpack2(acc[i][0]);
        float2 q = unpack2(acc[i][1]);
        float4 v = make_float4(p.x, p.y, q.x, q.y);
        *(float4*)(out + (size_t)(m0 + ty * 4 + i) * 256 + h0 + tx * 4) = v;
    }
}

// ---------------------------------------------------------------------------
// Kernel 2 (v3): recurrence, 2-CTA cluster per batch, data-flag signaling.
//
// CTA rank r owns outputs o in [128r, 128r+128). Output o is handled by a
// thread PAIR: low thread i (=o-128r) covers local k-half (h values this CTA
// computed itself); high thread i+128 covers the remote k-half (peer h,
// delivered by the peer's low warps via st.shared::cluster into h_peer[],
// signaled by 4 per-warp monotonic flags with release/acquire semantics).
//
// Per-step chain: low tanh+push -> fabric -> high flag poll (chunked: FMA
// each 32-value chunk as it lands) -> part[] + bar.arrive -> low bar.sync,
// tanh -> push. High threads never block on a barrier; low's local-k FMA
// overlaps the crossing.
// ---------------------------------------------------------------------------
__global__ void __launch_bounds__(256, 1) __cluster_dims__(2, 1, 1)
rnn_scan(const float* __restrict__ Whh, float* __restrict__ io,
         float* __restrict__ hn) {
    __shared__ alignas(16) float h_own[128];       // this CTA's h (single buf)
    __shared__ alignas(16) float h_peer[2][128];   // peer h (DSMEM target)
    __shared__ alignas(16) float part[2][128];     // remote-k partials
    __shared__ alignas(16) unsigned flags[2][4];   // per-producer-warp counters

    unsigned rank;
    asm("mov.u32 %0, %%cluster_ctarank;" : "=r"(rank));
    const unsigned peer = rank ^ 1u;
    const int t = threadIdx.x;
    const int b = blockIdx.x >> 1;
    const bool low = t < 128;
    const int i = t & 127;
    const int o = (int)rank * 128 + i;           // output index of this pair
    const int kbase = low ? (int)rank * 128 : (int)peer * 128;

    // W[o][kbase .. kbase+128) in registers (64 fma2 words)
    unsigned long long w[64];
    {
        const float4* wrow = (const float4*)(Whh + (size_t)o * 256 + kbase);
#pragma unroll
        for (int j = 0; j < 32; j++) {
            float4 v = wrow[j];
            w[2 * j]     = pack2(v.x, v.y);
            w[2 * j + 1] = pack2(v.z, v.w);
        }
    }

    // init: h0 = 0, flags = 0
    if (low) { h_own[i] = 0.0f; h_peer[1][i] = 0.0f; h_peer[0][i] = 0.0f; }
    if (t < 8) ((unsigned*)flags)[t] = 0u;
    __syncthreads();
    cluster_sync_all();   // peer sees our zeroed buffers before pushing

    // producer-side peer addresses (low threads push h + flags)
    const int lw = i >> 5;        // low warp id 0..3 (chunk id)
    unsigned hpush[2], fpush[2];
    if (low) {
        hpush[0] = mapa_peer(smem_u32(&h_peer[0][i]), peer);
        hpush[1] = mapa_peer(smem_u32(&h_peer[1][i]), peer);
        fpush[0] = mapa_peer(smem_u32(&flags[0][lw]), peer);
        fpush[1] = mapa_peer(smem_u32(&flags[1][lw]), peer);
    }

    float* xrow = io + (size_t)b * S_LEN * HID + o;
    float xw_cur = 0.0f, xw_nxt = 0.0f;
    if (low) { xw_cur = xrow[0]; xw_nxt = xrow[HID]; }

    for (int s = 0; s < S_LEN; s++) {
        const int buf = s & 1;

        if (low) {
            // ---- local-k dot over h_own (available immediately) ----
            const ulonglong2* h2 = (const ulonglong2*)h_own;
            unsigned long long a0 = 0ull, a1 = 0ull, a2 = 0ull, a3 = 0ull;
#pragma unroll
            for (int j = 0; j < 16; j++) {
                ulonglong2 v0 = h2[2 * j];
                ulonglong2 v1 = h2[2 * j + 1];
                a0 = fma2(w[4 * j],     v0.x, a0);
                a1 = fma2(w[4 * j + 1], v0.y, a1);
                a2 = fma2(w[4 * j + 2], v1.x, a2);
                a3 = fma2(w[4 * j + 3], v1.y, a3);
            }
            a0 = add2(a0, a1); a2 = add2(a2, a3); a0 = add2(a0, a2);
            float2 p = unpack2(a0);
            float local_sum = p.x + p.y;

            bar_sync(0, 256);  // wait for high's part[buf]

            float v = tanhf(local_sum + part[buf][i] + xw_cur);

            // push h(s) to peer buf[s&1]; flag value s+1 (monotonic)
            st_cluster_f32(hpush[buf], v);
            __syncwarp();
            if ((i & 31) == 0) st_release_cluster_u32(fpush[buf], (unsigned)(s + 1));

            h_own[i] = v;                    // safe: all low FMA reads done (bar0)
            xrow[(size_t)s * HID] = v;       // output[b][s][o]
            if (s == S_LEN - 1) hn[(size_t)b * HID + o] = v;

            xw_cur = xw_nxt;
            xw_nxt = (s + 2 < S_LEN) ? xrow[(size_t)(s + 2) * HID] : 0.0f;

            bar_sync(1, 128);  // low-only: h_own(s) visible before next FMA
        } else {
            // ---- remote-k dot, chunked by producer warp arrival ----
            const int rbuf = buf ^ 1;        // peer pushed h(s-1) into buf[(s-1)&1]
            const unsigned target = (unsigned)s;
            unsigned long long a0 = 0ull, a1 = 0ull, a2 = 0ull, a3 = 0ull;
#pragma unroll
            for (int c = 0; c < 4; c++) {
                const unsigned fa = smem_u32(&flags[rbuf][c]);
                while (ld_acquire_cluster_u32(fa) < target) { }
                const ulonglong2* h2 =
                    (const ulonglong2*)(&h_peer[rbuf][32 * c]);
#pragma unroll
                for (int j = 0; j < 4; j++) {
                    ulonglong2 v0 = h2[2 * j];
                    ulonglong2 v1 = h2[2 * j + 1];
                    a0 = fma2(w[16 * c + 4 * j],     v0.x, a0);
                    a1 = fma2(w[16 * c + 4 * j + 1], v0.y, a1);
                    a2 = fma2(w[16 * c + 4 * j + 2], v1.x, a2);
                    a3 = fma2(w[16 * c + 4 * j + 3], v1.y, a3);
                }
            }
            a0 = add2(a0, a1); a2 = add2(a2, a3); a0 = add2(a0, a2);
            float2 p = unpack2(a0);
            part[buf][i] = p.x + p.y;

            bar_arrive(0, 256);  // release part[buf] to low; never blocks
        }
    }

    cluster_sync_all();  // peer DSMEM traffic drained before exit
}

// ---------------------------------------------------------------------------
extern "C" void kernel_launch(void* const* d_in, const int* in_sizes, int n_in,
                              void* d_out, int out_size) {
    (void)in_sizes; (void)n_in; (void)out_size;
    const float* x   = (const float*)d_in[0];  // [64, 2048, 256]
    const float* wih = (const float*)d_in[1];  // [256, 256]
    const float* whh = (const float*)d_in[2];  // [256, 256]
    float* out = (float*)d_out;                           // output [64,2048,256]
    float* hn  = out + (size_t)BATCH * S_LEN * HID;       // h_n [1,64,256]

    dim3 grid_gemm(BATCH * S_LEN / 64, HID / 64);
    xw_gemm<<<grid_gemm, 256>>>(x, wih, out);

    rnn_scan<<<BATCH * 2, 256>>>(whh, out, hn);
}

// round 4
// speedup vs baseline: 1.1529x; 1.1529x over previous
#include <cuda_runtime.h>
#include <cstdint>

#define BATCH 64
#define S_LEN 2048
#define HID   256

// ---------------------------------------------------------------------------
// f32x2 packed-math helpers
// ---------------------------------------------------------------------------
__device__ __forceinline__ unsigned long long fma2(unsigned long long a,
                                                   unsigned long long b,
                                                   unsigned long long c) {
    unsigned long long d;
    asm("fma.rn.f32x2 %0, %1, %2, %3;" : "=l"(d) : "l"(a), "l"(b), "l"(c));
    return d;
}
__device__ __forceinline__ unsigned long long add2(unsigned long long a,
                                                   unsigned long long b) {
    unsigned long long d;
    asm("add.rn.f32x2 %0, %1, %2;" : "=l"(d) : "l"(a), "l"(b));
    return d;
}
__device__ __forceinline__ unsigned long long pack2(float x, float y) {
    unsigned long long r;
    asm("mov.b64 %0, {%1, %2};" : "=l"(r) : "f"(x), "f"(y));
    return r;
}
__device__ __forceinline__ float2 unpack2(unsigned long long v) {
    float2 r;
    asm("mov.b64 {%0, %1}, %2;" : "=f"(r.x), "=f"(r.y) : "l"(v));
    return r;
}

// ---------------------------------------------------------------------------
// Kernel 1: xW = X @ W_ih^T   (131072x256 @ 256x256) fp32, written into d_out
// ---------------------------------------------------------------------------
__global__ void __launch_bounds__(256) xw_gemm(const float* __restrict__ X,
                                               const float* __restrict__ Wih,
                                               float* __restrict__ out) {
    __shared__ alignas(16) float Xs[32][68];
    __shared__ alignas(16) float Ws[32][68];

    const int tid = threadIdx.x;
    const int m0  = blockIdx.x * 64;
    const int h0  = blockIdx.y * 64;
    const int row = tid >> 2;
    const int c4  = tid & 3;
    const int tx  = tid & 15;
    const int ty  = tid >> 4;

    unsigned long long acc[4][2];
#pragma unroll
    for (int i = 0; i < 4; i++) { acc[i][0] = 0ull; acc[i][1] = 0ull; }

    const float* Xbase = X   + (size_t)(m0 + row) * 256;
    const float* Wbase = Wih + (size_t)(h0 + row) * 256;

    float4 xa = *(const float4*)(Xbase + 0  + c4 * 4);
    float4 xb = *(const float4*)(Xbase + 16 + c4 * 4);
    float4 wa = *(const float4*)(Wbase + 0  + c4 * 4);
    float4 wb = *(const float4*)(Wbase + 16 + c4 * 4);

#pragma unroll 1
    for (int k0 = 0; k0 < 256; k0 += 32) {
        __syncthreads();
#pragma unroll
        for (int e = 0; e < 4; e++) {
            Xs[c4 * 4 + e][row]      = (&xa.x)[e];
            Xs[16 + c4 * 4 + e][row] = (&xb.x)[e];
            Ws[c4 * 4 + e][row]      = (&wa.x)[e];
            Ws[16 + c4 * 4 + e][row] = (&wb.x)[e];
        }
        float4 nxa = make_float4(0, 0, 0, 0), nxb = nxa, nwa = nxa, nwb = nxa;
        if (k0 < 224) {
            nxa = *(const float4*)(Xbase + k0 + 32 + c4 * 4);
            nxb = *(const float4*)(Xbase + k0 + 48 + c4 * 4);
            nwa = *(const float4*)(Wbase + k0 + 32 + c4 * 4);
            nwb = *(const float4*)(Wbase + k0 + 48 + c4 * 4);
        }
        __syncthreads();

#pragma unroll
        for (int kk = 0; kk < 32; kk++) {
            float4 a4 = *(const float4*)(&Xs[kk][ty * 4]);
            const unsigned long long* bp =
                (const unsigned long long*)(&Ws[kk][tx * 4]);
            unsigned long long b0 = bp[0];
            unsigned long long b1 = bp[1];
            unsigned long long aa;
            aa = pack2(a4.x, a4.x);
            acc[0][0] = fma2(aa, b0, acc[0][0]); acc[0][1] = fma2(aa, b1, acc[0][1]);
            aa = pack2(a4.y, a4.y);
            acc[1][0] = fma2(aa, b0, acc[1][0]); acc[1][1] = fma2(aa, b1, acc[1][1]);
            aa = pack2(a4.z, a4.z);
            acc[2][0] = fma2(aa, b0, acc[2][0]); acc[2][1] = fma2(aa, b1, acc[2][1]);
            aa = pack2(a4.w, a4.w);
            acc[3][0] = fma2(aa, b0, acc[3][0]); acc[3][1] = fma2(aa, b1, acc[3][1]);
        }
        xa = nxa; xb = nxb; wa = nwa; wb = nwb;
    }

#pragma unroll
    for (int i = 0; i < 4; i++) {
        float2 p = unpack2(acc[i][0]);
        float2 q = unpack2(acc[i][1]);
        float4 v = make_float4(p.x, p.y, q.x, q.y);
        *(float4*)(out + (size_t)(m0 + ty * 4 + i) * 256 + h0 + tx * 4) = v;
    }
}

// ---------------------------------------------------------------------------
// Kernel 2 (v4): recurrence, ONE CTA per batch element. No cluster, no
// cross-CTA traffic. Thread t owns output row o = t:
//   k = 0..191  : W in registers (96 fma2 operand words)
//   k = 192..255: W in smem, transposed pair layout Ws2[pair][o] (LDS.64,
//                 lane-consecutive, conflict-free)
// h double-buffered in smem (broadcast LDS.128 reads). One __syncthreads per
// step. Critical path = fma2 issue (~512 cyc/step) instead of DSMEM crossing.
// ---------------------------------------------------------------------------
#define WREG_PAIRS 96   // 192 floats of W in registers
#define WSM_PAIRS  32   // 64  floats of W in smem (32 packed pairs)

__global__ void __launch_bounds__(256, 1)
rnn_scan(const float* __restrict__ Whh, float* __restrict__ io,
         float* __restrict__ hn) {
    extern __shared__ unsigned long long Ws2[];      // [WSM_PAIRS][256]
    __shared__ alignas(16) float hbuf[2][HID];       // double-buffered h

    const int t = threadIdx.x;          // output index o = t
    const int b = blockIdx.x;

    // W[t][0..191] into registers as f32x2 words
    unsigned long long w[WREG_PAIRS];
    {
        const float4* wrow = (const float4*)(Whh + (size_t)t * 256);
#pragma unroll
        for (int j = 0; j < WREG_PAIRS / 2; j++) {   // 48 x float4
            float4 v = wrow[j];
            w[2 * j]     = pack2(v.x, v.y);
            w[2 * j + 1] = pack2(v.z, v.w);
        }
    }
    // W[t][192..255] into smem: Ws2[p][t] = (W[t][192+2p], W[t][193+2p])
    {
        const unsigned long long* wrow2 =
            (const unsigned long long*)(Whh + (size_t)t * 256);
#pragma unroll
        for (int p = 0; p < WSM_PAIRS; p++)
            Ws2[p * 256 + t] = wrow2[96 + p];
    }

    hbuf[0][t] = 0.0f;                  // h0 = 0
    __syncthreads();

    float* xcol = io + (size_t)b * S_LEN * HID + t;   // column t, stride HID
    float xw0 = xcol[0];
    float xw1 = xcol[HID];

    for (int s = 0; s < S_LEN; s++) {
        const ulonglong2* h2 = (const ulonglong2*)hbuf[s & 1];

        unsigned long long a0 = 0ull, a1 = 0ull, a2 = 0ull, a3 = 0ull;
        // k = 0..191 from registers
#pragma unroll
        for (int j = 0; j < 48; j++) {
            ulonglong2 v = h2[j];                     // broadcast LDS.128
            a0 = fma2(w[2 * j],     v.x, a0);
            a1 = fma2(w[2 * j + 1], v.y, a1);
        }
        // k = 192..255 from smem (conflict-free LDS.64 per pair)
#pragma unroll
        for (int p = 0; p < 16; p++) {
            ulonglong2 v = h2[48 + p];
            a2 = fma2(Ws2[(2 * p)     * 256 + t], v.x, a2);
            a3 = fma2(Ws2[(2 * p + 1) * 256 + t], v.y, a3);
        }
        a0 = add2(a0, a1); a2 = add2(a2, a3); a0 = add2(a0, a2);
        float2 pp = unpack2(a0);

        float v = tanhf(pp.x + pp.y + xw0);

        hbuf[(s + 1) & 1][t] = v;          // next step's h (other buffer)
        xcol[(size_t)s * HID] = v;         // output[b][s][t] (in place)
        if (s == S_LEN - 1) hn[(size_t)b * HID + t] = v;

        xw0 = xw1;
        xw1 = (s + 2 < S_LEN) ? xcol[(size_t)(s + 2) * HID] : 0.0f;

        __syncthreads();                   // h(s) visible before step s+1 reads
    }
}

// ---------------------------------------------------------------------------
extern "C" void kernel_launch(void* const* d_in, const int* in_sizes, int n_in,
                              void* d_out, int out_size) {
    (void)in_sizes; (void)n_in; (void)out_size;
    const float* x   = (const float*)d_in[0];  // [64, 2048, 256]
    const float* wih = (const float*)d_in[1];  // [256, 256]
    const float* whh = (const float*)d_in[2];  // [256, 256]
    float* out = (float*)d_out;                           // output [64,2048,256]
    float* hn  = out + (size_t)BATCH * S_LEN * HID;       // h_n [1,64,256]

    dim3 grid_gemm(BATCH * S_LEN / 64, HID / 64);
    xw_gemm<<<grid_gemm, 256>>>(x, wih, out);

    const int smem_bytes = WSM_PAIRS * 256 * (int)sizeof(unsigned long long);
    cudaFuncSetAttribute(rnn_scan,
                         cudaFuncAttributeMaxDynamicSharedMemorySize,
                         smem_bytes);
    rnn_scan<<<BATCH, 256, smem_bytes>>>(whh, out, hn);
}